// round 2
// baseline (speedup 1.0000x reference)
#include <cuda_runtime.h>
#include <cuda_bf16.h>
#include <math.h>

#define N_TOKENS 16384
#define D_MODEL  512
#define NQ       10
#define NL       2
#define DIM      1024   // 2^NQ

// ---------------- scratch (device globals; no allocations allowed) ----------
__device__ __align__(16) float g_Ur[DIM * DIM];
__device__ __align__(16) float g_Ui[DIM * DIM];
__device__ __align__(16) float g_xq[N_TOKENS * DIM];   // xq, then psi (in-place normalize)
__device__ __align__(16) float g_re[N_TOKENS * DIM];   // re, then probs (in-place)
__device__ __align__(16) float g_im[N_TOKENS * DIM];
__device__ __align__(16) float g_out[N_TOKENS * D_MODEL];

// ---------------- complex helpers -------------------------------------------
__device__ __forceinline__ float2 cmul(float2 a, float2 b) {
    return make_float2(a.x * b.x - a.y * b.y, a.x * b.y + a.y * b.x);
}
__device__ __forceinline__ float2 cadd(float2 a, float2 b) {
    return make_float2(a.x + b.x, a.y + b.y);
}

// ---------------- kernel 1: build circuit unitary ---------------------------
// Block j simulates basis state e_j through the circuit -> column U[:, j].
// State (1024 complex) lives in shared memory; 60 rotations folded into 20
// combined 2x2 complex gates (Rz*Ry*Rx per qubit per layer) + CZ phase passes.
__global__ void build_unitary(const float* __restrict__ rot,
                              const float* __restrict__ ent,
                              float* __restrict__ Ur, float* __restrict__ Ui) {
    __shared__ float2 st[DIM];
    const int j = blockIdx.x;
    const int t = threadIdx.x;   // 256 threads

    for (int i = t; i < DIM; i += 256)
        st[i] = make_float2(i == j ? 1.f : 0.f, 0.f);
    __syncthreads();

    for (int l = 0; l < NL; l++) {
        for (int q = 0; q < NQ; q++) {
            const float t1 = rot[(l * NQ + q) * 3 + 0];
            const float t2 = rot[(l * NQ + q) * 3 + 1];
            const float t3 = rot[(l * NQ + q) * 3 + 2];
            // Rx
            float c1, s1; sincosf(0.5f * t1, &s1, &c1);
            float2 rx00 = {c1, 0.f}, rx01 = {0.f, -s1}, rx10 = {0.f, -s1}, rx11 = {c1, 0.f};
            // Ry
            float c2, s2; sincosf(0.5f * t2, &s2, &c2);
            float2 ry00 = {c2, 0.f}, ry01 = {-s2, 0.f}, ry10 = {s2, 0.f}, ry11 = {c2, 0.f};
            // A = Ry * Rx
            float2 a00 = cadd(cmul(ry00, rx00), cmul(ry01, rx10));
            float2 a01 = cadd(cmul(ry00, rx01), cmul(ry01, rx11));
            float2 a10 = cadd(cmul(ry10, rx00), cmul(ry11, rx10));
            float2 a11 = cadd(cmul(ry10, rx01), cmul(ry11, rx11));
            // M = Rz * A   (Rz = diag(e^{-i t3/2}, e^{+i t3/2}))
            float cz, sz; sincosf(0.5f * t3, &sz, &cz);
            float2 ez0 = {cz, -sz}, ez1 = {cz, sz};
            float2 m00 = cmul(ez0, a00), m01 = cmul(ez0, a01);
            float2 m10 = cmul(ez1, a10), m11 = cmul(ez1, a11);

            const int mask = 1 << (NQ - 1 - q);
            for (int p = t; p < DIM / 2; p += 256) {
                int i0 = ((p & ~(mask - 1)) << 1) | (p & (mask - 1));
                int i1 = i0 | mask;
                float2 v0 = st[i0], v1 = st[i1];
                st[i0] = cadd(cmul(m00, v0), cmul(m01, v1));
                st[i1] = cadd(cmul(m10, v0), cmul(m11, v1));
            }
            __syncthreads();
        }
        // parameterized CZ chain: combine all 9 phases in one pass
        for (int i = t; i < DIM; i += 256) {
            float ang = 0.f;
            #pragma unroll
            for (int g = 0; g < NQ - 1; g++) {
                int b1 = (i >> (NQ - 1 - g)) & 1;
                int b2 = (i >> (NQ - 2 - g)) & 1;
                if (b1 & b2) ang += ent[l * (NQ - 1) + g];
            }
            float sn, cs; sincosf(ang, &sn, &cs);
            st[i] = cmul(st[i], make_float2(cs, sn));
        }
        __syncthreads();
    }

    for (int i = t; i < DIM; i += 256) {
        Ur[i * DIM + j] = st[i].x;
        Ui[i * DIM + j] = st[i].y;
    }
}

// ---------------- kernel 2: fp32 SGEMM (NT): C[m,n] = sum_k A[m,k]*B[n,k] ---
// 128x128 tile, BK=8, 256 threads, 8x8 per thread. M,N,K multiples of 128/8.
__global__ __launch_bounds__(256, 2)
void sgemm_nt(const float* __restrict__ A, const float* __restrict__ B,
              float* __restrict__ C, int M, int N, int K,
              const float* __restrict__ bias) {
    __shared__ float As[8][128];
    __shared__ float Bs[8][128];

    const int tid = threadIdx.x;
    const int tx = tid & 15;          // 16 cols of threads
    const int ty = tid >> 4;          // 16 rows of threads
    const int bm = blockIdx.y * 128;
    const int bn = blockIdx.x * 128;

    const int lr = tid >> 1;          // 0..127: row within tile for loading
    const int lk = (tid & 1) * 4;     // 0 or 4: K offset for float4 load

    const float* Aptr = A + (size_t)(bm + lr) * K + lk;
    const float* Bptr = B + (size_t)(bn + lr) * K + lk;

    float acc[8][8];
    #pragma unroll
    for (int i = 0; i < 8; i++)
        #pragma unroll
        for (int jj = 0; jj < 8; jj++) acc[i][jj] = 0.f;

    for (int k0 = 0; k0 < K; k0 += 8) {
        float4 av = *(const float4*)(Aptr + k0);
        float4 bv = *(const float4*)(Bptr + k0);
        __syncthreads();
        As[lk + 0][lr] = av.x; As[lk + 1][lr] = av.y;
        As[lk + 2][lr] = av.z; As[lk + 3][lr] = av.w;
        Bs[lk + 0][lr] = bv.x; Bs[lk + 1][lr] = bv.y;
        Bs[lk + 2][lr] = bv.z; Bs[lk + 3][lr] = bv.w;
        __syncthreads();

        #pragma unroll
        for (int k = 0; k < 8; k++) {
            float a[8], b[8];
            *(float4*)(a)     = *(const float4*)&As[k][ty * 8];
            *(float4*)(a + 4) = *(const float4*)&As[k][ty * 8 + 4];
            *(float4*)(b)     = *(const float4*)&Bs[k][tx * 8];
            *(float4*)(b + 4) = *(const float4*)&Bs[k][tx * 8 + 4];
            #pragma unroll
            for (int i = 0; i < 8; i++)
                #pragma unroll
                for (int jj = 0; jj < 8; jj++)
                    acc[i][jj] = fmaf(a[i], b[jj], acc[i][jj]);
        }
    }

    #pragma unroll
    for (int i = 0; i < 8; i++) {
        int m = bm + ty * 8 + i;
        #pragma unroll
        for (int jj = 0; jj < 8; jj++) {
            int n = bn + tx * 8 + jj;
            float v = acc[i][jj];
            if (bias) v += bias[n];
            C[(size_t)m * N + n] = v;
        }
    }
}

// ---------------- block reduce ----------------------------------------------
__device__ float blockReduceSum256(float v) {
    __shared__ float sh[8];
    __syncthreads();   // protect sh reuse across consecutive calls
    int lane = threadIdx.x & 31, wid = threadIdx.x >> 5;
    #pragma unroll
    for (int o = 16; o > 0; o >>= 1) v += __shfl_down_sync(0xffffffffu, v, o);
    if (lane == 0) sh[wid] = v;
    __syncthreads();
    float s = 0.f;
    if (threadIdx.x < 8) s = sh[threadIdx.x];
    if (wid == 0) {
        #pragma unroll
        for (int o = 4; o > 0; o >>= 1) s += __shfl_down_sync(0xffu, s, o);
        if (lane == 0) sh[0] = s;
    }
    __syncthreads();
    return sh[0];
}

// ---------------- kernel 3: row L2-normalize (in place, width 1024) ---------
__global__ void rownorm(float* __restrict__ xq) {
    const int row = blockIdx.x;
    float* p = xq + (size_t)row * DIM;
    const int t = threadIdx.x;
    float v0 = p[t], v1 = p[t + 256], v2 = p[t + 512], v3 = p[t + 768];
    float ss = blockReduceSum256(v0 * v0 + v1 * v1 + v2 * v2 + v3 * v3);
    float scale = 1.f / fmaxf(sqrtf(ss), 1e-12f);
    p[t] = v0 * scale; p[t + 256] = v1 * scale;
    p[t + 512] = v2 * scale; p[t + 768] = v3 * scale;
}

// ---------------- kernel 4: probs = re^2 + im^2 (in place into re) ----------
__global__ void probs_kernel(float* __restrict__ re, const float* __restrict__ im) {
    const size_t n = (size_t)N_TOKENS * DIM / 4;
    size_t i = blockIdx.x * (size_t)blockDim.x + threadIdx.x;
    size_t stride = (size_t)gridDim.x * blockDim.x;
    float4* r4 = (float4*)re;
    const float4* i4 = (const float4*)im;
    for (; i < n; i += stride) {
        float4 r = r4[i], m = i4[i];
        r.x = r.x * r.x + m.x * m.x;
        r.y = r.y * r.y + m.y * m.y;
        r.z = r.z * r.z + m.z * m.z;
        r.w = r.w * r.w + m.w * m.w;
        r4[i] = r;
    }
}

// ---------------- kernel 5: LayerNorm(512) -> d_out --------------------------
__global__ void layernorm(const float* __restrict__ in,
                          const float* __restrict__ w, const float* __restrict__ b,
                          float* __restrict__ out) {
    const int row = blockIdx.x;
    const float* p = in + (size_t)row * D_MODEL;
    const int t = threadIdx.x;
    float v0 = p[t], v1 = p[t + 256];
    float mu = blockReduceSum256(v0 + v1) * (1.f / D_MODEL);
    float d0 = v0 - mu, d1 = v1 - mu;
    float var = blockReduceSum256(d0 * d0 + d1 * d1) * (1.f / D_MODEL);
    float inv = rsqrtf(var + 1e-5f);
    float* o = out + (size_t)row * D_MODEL;
    o[t]       = d0 * inv * w[t]       + b[t];
    o[t + 256] = d1 * inv * w[t + 256] + b[t + 256];
}

// ---------------- launch ------------------------------------------------------
extern "C" void kernel_launch(void* const* d_in, const int* in_sizes, int n_in,
                              void* d_out, int out_size) {
    const float* x     = (const float*)d_in[0];
    const float* W_in  = (const float*)d_in[1];
    const float* b_in  = (const float*)d_in[2];
    const float* W_out = (const float*)d_in[3];
    const float* b_out = (const float*)d_in[4];
    const float* rot   = (const float*)d_in[5];
    const float* ent   = (const float*)d_in[6];
    const float* ln_w  = (const float*)d_in[7];
    const float* ln_b  = (const float*)d_in[8];
    float* out = (float*)d_out;

    float *Ur, *Ui, *xq, *re, *im, *pre;
    cudaGetSymbolAddress((void**)&Ur,  g_Ur);
    cudaGetSymbolAddress((void**)&Ui,  g_Ui);
    cudaGetSymbolAddress((void**)&xq,  g_xq);
    cudaGetSymbolAddress((void**)&re,  g_re);
    cudaGetSymbolAddress((void**)&im,  g_im);
    cudaGetSymbolAddress((void**)&pre, g_out);

    // 1) circuit unitary (1024 x 1024 complex, split into Ur/Ui)
    build_unitary<<<DIM, 256>>>(rot, ent, Ur, Ui);

    // 2) xq = x @ W_in^T + b_in
    sgemm_nt<<<dim3(DIM / 128, N_TOKENS / 128), 256>>>(x, W_in, xq,
                                                       N_TOKENS, DIM, D_MODEL, b_in);
    // 3) psi = normalize(xq) (in place)
    rownorm<<<N_TOKENS, 256>>>(xq);

    // 4) re = psi @ Ur^T ; im = psi @ Ui^T
    sgemm_nt<<<dim3(DIM / 128, N_TOKENS / 128), 256>>>(xq, Ur, re,
                                                       N_TOKENS, DIM, DIM, nullptr);
    sgemm_nt<<<dim3(DIM / 128, N_TOKENS / 128), 256>>>(xq, Ui, im,
                                                       N_TOKENS, DIM, DIM, nullptr);
    // 5) probs = re^2 + im^2 (into re)
    probs_kernel<<<4096, 256>>>(re, im);

    // 6) pre = probs @ W_out^T + b_out
    sgemm_nt<<<dim3(D_MODEL / 128, N_TOKENS / 128), 256>>>(re, W_out, pre,
                                                           N_TOKENS, D_MODEL, DIM, b_out);
    // 7) LayerNorm -> d_out
    layernorm<<<N_TOKENS, 256>>>(pre, ln_w, ln_b, out);
}

// round 4
// speedup vs baseline: 2.5886x; 2.5886x over previous
#include <cuda_runtime.h>
#include <cuda_bf16.h>
#include <math.h>
#include <stdint.h>

#define N_TOKENS 16384
#define D_MODEL  512
#define NQ       10
#define NL       2
#define DIM      1024
#define K1       1536   // 3*512
#define K2       3072   // 3*1024

#define BM 128
#define BN 128
#define BKB 128                    // K bytes per stage (64 bf16)
#define NSTAGES 5
#define TILE_B (BM*BKB)            // 16 KB per operand tile
#define STAGE_B (2*TILE_B)         // 32 KB
#define SMEM_TOTAL (NSTAGES*STAGE_B)   // 160 KB

__device__ __align__(16) float          g_Ur[DIM*DIM];
__device__ __align__(16) float          g_Ui[DIM*DIM];
__device__ __align__(16) float          g_xq[N_TOKENS*DIM];
__device__ __align__(16) float          g_pre[N_TOKENS*D_MODEL];
__device__ __align__(16) __nv_bfloat16  g_xs[N_TOKENS*K1];
__device__ __align__(16) __nv_bfloat16  g_Wins[DIM*K1];
__device__ __align__(16) __nv_bfloat16  g_psis[N_TOKENS*K2];
__device__ __align__(16) __nv_bfloat16  g_U2[2048*K2];
__device__ __align__(16) __nv_bfloat16  g_P[N_TOKENS*K2];
__device__ __align__(16) __nv_bfloat16  g_Wouts[D_MODEL*K2];

// ---------------- PTX helpers (all non-'a' features: sm_80-era) -------------
__device__ __forceinline__ uint32_t smem_u32(const void* p) {
    return (uint32_t)__cvta_generic_to_shared(p);
}
#define CP16(saddr, gaddr) \
    asm volatile("cp.async.cg.shared.global [%0], [%1], 16;" \
                 :: "r"(saddr), "l"(gaddr) : "memory")
#define CP_COMMIT() asm volatile("cp.async.commit_group;" ::: "memory")
#define CP_WAIT3()  asm volatile("cp.async.wait_group 3;" ::: "memory")

#define LDSM4(r0,r1,r2,r3,addr) \
    asm volatile("ldmatrix.sync.aligned.m8n8.x4.shared.b16 {%0,%1,%2,%3}, [%4];" \
                 : "=r"(r0), "=r"(r1), "=r"(r2), "=r"(r3) : "r"(addr))

#define MMA16816(c, a0,a1,a2,a3, b0,b1) \
    asm volatile("mma.sync.aligned.m16n8k16.row.col.f32.bf16.bf16.f32 " \
                 "{%0,%1,%2,%3}, {%4,%5,%6,%7}, {%8,%9}, {%0,%1,%2,%3};" \
                 : "+f"((c)[0]), "+f"((c)[1]), "+f"((c)[2]), "+f"((c)[3]) \
                 : "r"(a0), "r"(a1), "r"(a2), "r"(a3), "r"(b0), "r"(b1))

#define SW128(off) ((off) ^ (((off) >> 3) & 0x70))

// ---------------- bf16 mma GEMM ----------------------------------------------
// C[M,N] = A[M,Kp] @ B[N,Kp]^T ; A,B bf16 K-major. EPI=0: C fp32 (+bias).
// EPI=1: output cols are (re,im) pairs -> prob = re^2+im^2, split to bf16
//        hi/lo and written to P[M,K2] segments [hi|hi|lo].
template<int EPI>
__global__ __launch_bounds__(256, 1)
void gemm_mma(const __nv_bfloat16* __restrict__ A,
              const __nv_bfloat16* __restrict__ B,
              float* __restrict__ C,
              __nv_bfloat16* __restrict__ P,
              const float* __restrict__ bias,
              int M, int N, int Kp)
{
    extern __shared__ char smem[];
    const uint32_t S0 = smem_u32(smem);
    const int tid  = threadIdx.x;
    const int wid  = tid >> 5;
    const int lane = tid & 31;
    const int warp_m = (wid & 3) * 32;   // 4 warps along M
    const int warp_n = (wid >> 2) * 64;  // 2 warps along N
    const int m0 = blockIdx.y * BM;
    const int n0 = blockIdx.x * BN;
    const int nks = Kp / 64;

    const size_t ldb = (size_t)Kp * 2;
    const size_t Ab = (size_t)__cvta_generic_to_global(A) + (size_t)m0 * ldb;
    const size_t Bb = (size_t)__cvta_generic_to_global(B) + (size_t)n0 * ldb;
    const int lrow = tid >> 3;            // 0..31
    const int lcol = (tid & 7) * 16;      // 16B chunk within 128B row

    float c[2][8][4];
    #pragma unroll
    for (int mt = 0; mt < 2; mt++)
        #pragma unroll
        for (int nt = 0; nt < 8; nt++)
            #pragma unroll
            for (int j = 0; j < 4; j++) c[mt][nt][j] = 0.f;

    // ---- prologue: issue NSTAGES-1 stages ----
    #pragma unroll
    for (int s = 0; s < NSTAGES - 1; s++) {
        const uint32_t saA = S0 + s * STAGE_B;
        const uint32_t saB = saA + TILE_B;
        const size_t ka = Ab + (size_t)s * BKB;
        const size_t kb = Bb + (size_t)s * BKB;
        #pragma unroll
        for (int i = 0; i < 4; i++) {
            int r = lrow + i * 32;
            CP16(saA + SW128(r*128 + lcol), ka + (size_t)r * ldb + lcol);
            CP16(saB + SW128(r*128 + lcol), kb + (size_t)r * ldb + lcol);
        }
        CP_COMMIT();
    }

    // ---- mainloop ----
    for (int ks = 0; ks < nks; ks++) {
        CP_WAIT3();
        __syncthreads();

        // issue loads for stage ks+NSTAGES-1 into slot (ks-1)%NSTAGES
        int ld = ks + NSTAGES - 1;
        if (ld < nks) {
            int slot = ld % NSTAGES;
            const uint32_t saA = S0 + slot * STAGE_B;
            const uint32_t saB = saA + TILE_B;
            const size_t ka = Ab + (size_t)ld * BKB;
            const size_t kb = Bb + (size_t)ld * BKB;
            #pragma unroll
            for (int i = 0; i < 4; i++) {
                int r = lrow + i * 32;
                CP16(saA + SW128(r*128 + lcol), ka + (size_t)r * ldb + lcol);
                CP16(saB + SW128(r*128 + lcol), kb + (size_t)r * ldb + lcol);
            }
        }
        CP_COMMIT();

        // compute on stage ks%NSTAGES
        const uint32_t saA = S0 + (ks % NSTAGES) * STAGE_B;
        const uint32_t saB = saA + TILE_B;
        #pragma unroll
        for (int kk = 0; kk < 4; kk++) {
            uint32_t a[2][4], b[4][4];
            #pragma unroll
            for (int mt = 0; mt < 2; mt++) {
                int r = warp_m + mt*16 + (lane & 15);
                uint32_t ad = saA + SW128(r*128 + kk*32 + ((lane >> 4) << 4));
                LDSM4(a[mt][0], a[mt][1], a[mt][2], a[mt][3], ad);
            }
            #pragma unroll
            for (int nt2 = 0; nt2 < 4; nt2++) {
                int r = warp_n + nt2*16 + (lane & 7) + ((lane >> 4) << 3);
                uint32_t bd = saB + SW128(r*128 + kk*32 + (((lane >> 3) & 1) << 4));
                LDSM4(b[nt2][0], b[nt2][1], b[nt2][2], b[nt2][3], bd);
            }
            #pragma unroll
            for (int mt = 0; mt < 2; mt++)
                #pragma unroll
                for (int nt = 0; nt < 8; nt++)
                    MMA16816(c[mt][nt], a[mt][0], a[mt][1], a[mt][2], a[mt][3],
                             b[nt >> 1][(nt & 1) * 2], b[nt >> 1][(nt & 1) * 2 + 1]);
        }
    }

    // ---- epilogue ----
    #pragma unroll
    for (int mt = 0; mt < 2; mt++) {
        int r0 = m0 + warp_m + mt*16 + (lane >> 2);
        #pragma unroll
        for (int nt = 0; nt < 8; nt++) {
            if (EPI == 0) {
                int nn = n0 + warp_n + nt*8 + 2*(lane & 3);
                float b0 = bias ? bias[nn] : 0.f;
                float b1 = bias ? bias[nn+1] : 0.f;
                float2 v0 = make_float2(c[mt][nt][0] + b0, c[mt][nt][1] + b1);
                float2 v1 = make_float2(c[mt][nt][2] + b0, c[mt][nt][3] + b1);
                *(float2*)(C + (size_t)r0 * N + nn) = v0;
                *(float2*)(C + (size_t)(r0+8) * N + nn) = v1;
            } else {
                int pcol = ((n0 + warp_n + nt*8) >> 1) + (lane & 3);
                float p0 = c[mt][nt][0]*c[mt][nt][0] + c[mt][nt][1]*c[mt][nt][1];
                float p1 = c[mt][nt][2]*c[mt][nt][2] + c[mt][nt][3]*c[mt][nt][3];
                __nv_bfloat16 h0 = __float2bfloat16(p0);
                __nv_bfloat16 l0 = __float2bfloat16(p0 - __bfloat162float(h0));
                __nv_bfloat16 h1 = __float2bfloat16(p1);
                __nv_bfloat16 l1 = __float2bfloat16(p1 - __bfloat162float(h1));
                __nv_bfloat16* pr0 = P + (size_t)r0 * K2 + pcol;
                __nv_bfloat16* pr1 = P + (size_t)(r0+8) * K2 + pcol;
                pr0[0] = h0; pr0[1024] = h0; pr0[2048] = l0;
                pr1[0] = h1; pr1[1024] = h1; pr1[2048] = l1;
            }
        }
    }
}

// ---------------- circuit unitary ---------------------------------------------
__device__ __forceinline__ float2 cmul(float2 a, float2 b) {
    return make_float2(a.x*b.x - a.y*b.y, a.x*b.y + a.y*b.x);
}
__device__ __forceinline__ float2 cadd(float2 a, float2 b) {
    return make_float2(a.x + b.x, a.y + b.y);
}

__global__ void build_unitary(const float* __restrict__ rot,
                              const float* __restrict__ ent,
                              float* __restrict__ Ur, float* __restrict__ Ui) {
    __shared__ float2 st[DIM];
    const int j = blockIdx.x;
    const int t = threadIdx.x;
    for (int i = t; i < DIM; i += 256)
        st[i] = make_float2(i == j ? 1.f : 0.f, 0.f);
    __syncthreads();
    for (int l = 0; l < NL; l++) {
        for (int q = 0; q < NQ; q++) {
            const float t1 = rot[(l*NQ + q)*3 + 0];
            const float t2 = rot[(l*NQ + q)*3 + 1];
            const float t3 = rot[(l*NQ + q)*3 + 2];
            float c1, s1; sincosf(0.5f*t1, &s1, &c1);
            float2 rx00 = {c1,0.f}, rx01 = {0.f,-s1}, rx10 = {0.f,-s1}, rx11 = {c1,0.f};
            float c2, s2; sincosf(0.5f*t2, &s2, &c2);
            float2 ry00 = {c2,0.f}, ry01 = {-s2,0.f}, ry10 = {s2,0.f}, ry11 = {c2,0.f};
            float2 a00 = cadd(cmul(ry00,rx00), cmul(ry01,rx10));
            float2 a01 = cadd(cmul(ry00,rx01), cmul(ry01,rx11));
            float2 a10 = cadd(cmul(ry10,rx00), cmul(ry11,rx10));
            float2 a11 = cadd(cmul(ry10,rx01), cmul(ry11,rx11));
            float cz, sz; sincosf(0.5f*t3, &sz, &cz);
            float2 ez0 = {cz,-sz}, ez1 = {cz,sz};
            float2 m00 = cmul(ez0,a00), m01 = cmul(ez0,a01);
            float2 m10 = cmul(ez1,a10), m11 = cmul(ez1,a11);
            const int mask = 1 << (NQ - 1 - q);
            for (int p = t; p < DIM/2; p += 256) {
                int i0 = ((p & ~(mask-1)) << 1) | (p & (mask-1));
                int i1 = i0 | mask;
                float2 v0 = st[i0], v1 = st[i1];
                st[i0] = cadd(cmul(m00,v0), cmul(m01,v1));
                st[i1] = cadd(cmul(m10,v0), cmul(m11,v1));
            }
            __syncthreads();
        }
        for (int i = t; i < DIM; i += 256) {
            float ang = 0.f;
            #pragma unroll
            for (int g = 0; g < NQ-1; g++) {
                int b1 = (i >> (NQ-1-g)) & 1;
                int b2 = (i >> (NQ-2-g)) & 1;
                if (b1 & b2) ang += ent[l*(NQ-1) + g];
            }
            float sn, cs; sincosf(ang, &sn, &cs);
            st[i] = cmul(st[i], make_float2(cs, sn));
        }
        __syncthreads();
    }
    for (int i = t; i < DIM; i += 256) {
        Ur[i*DIM + j] = st[i].x;
        Ui[i*DIM + j] = st[i].y;
    }
}

// ---------------- split / pack ------------------------------------------------
__device__ __forceinline__ void split2(float v, __nv_bfloat16& h, __nv_bfloat16& l) {
    h = __float2bfloat16(v);
    l = __float2bfloat16(v - __bfloat162float(h));
}

__global__ void split_x(const float* __restrict__ x, __nv_bfloat16* __restrict__ xs) {
    int i = blockIdx.x * blockDim.x + threadIdx.x;
    if (i >= N_TOKENS * D_MODEL) return;
    int m = i / D_MODEL, k = i % D_MODEL;
    __nv_bfloat16 h, l; split2(x[i], h, l);
    __nv_bfloat16* row = xs + (size_t)m * K1;
    row[k] = h; row[512 + k] = h; row[1024 + k] = l;
}

__global__ void split_Win(const float* __restrict__ W, __nv_bfloat16* __restrict__ Ws) {
    int i = blockIdx.x * blockDim.x + threadIdx.x;
    if (i >= DIM * D_MODEL) return;
    int n = i / D_MODEL, k = i % D_MODEL;
    __nv_bfloat16 h, l; split2(W[i], h, l);
    __nv_bfloat16* row = Ws + (size_t)n * K1;
    row[k] = h; row[512 + k] = l; row[1024 + k] = h;
}

__global__ void split_Wout(const float* __restrict__ W, __nv_bfloat16* __restrict__ Ws) {
    int i = blockIdx.x * blockDim.x + threadIdx.x;
    if (i >= D_MODEL * DIM) return;
    int n = i / DIM, k = i % DIM;
    __nv_bfloat16 h, l; split2(W[i], h, l);
    __nv_bfloat16* row = Ws + (size_t)n * K2;
    row[k] = h; row[1024 + k] = l; row[2048 + k] = h;
}

// U2 rows: 2j = Ur[j,:], 2j+1 = Ui[j,:]; cols [hi|lo|hi]
__global__ void pack_U(const float* __restrict__ Ur, const float* __restrict__ Ui,
                       __nv_bfloat16* __restrict__ U2) {
    int i = blockIdx.x * blockDim.x + threadIdx.x;
    if (i >= 2048 * DIM) return;
    int n = i / DIM, k = i % DIM;
    int j = n >> 1;
    float v = (n & 1) ? Ui[(size_t)j*DIM + k] : Ur[(size_t)j*DIM + k];
    __nv_bfloat16 h, l; split2(v, h, l);
    __nv_bfloat16* row = U2 + (size_t)n * K2;
    row[k] = h; row[1024 + k] = l; row[2048 + k] = h;
}

// ---------------- reductions ----------------------------------------------------
__device__ float blockReduceSum256(float v) {
    __shared__ float sh[8];
    __syncthreads();
    int lane = threadIdx.x & 31, wid = threadIdx.x >> 5;
    #pragma unroll
    for (int o = 16; o > 0; o >>= 1) v += __shfl_down_sync(0xffffffffu, v, o);
    if (lane == 0) sh[wid] = v;
    __syncthreads();
    float s = 0.f;
    if (threadIdx.x < 8) s = sh[threadIdx.x];
    if (wid == 0) {
        #pragma unroll
        for (int o = 4; o > 0; o >>= 1) s += __shfl_down_sync(0xffu, s, o);
        if (lane == 0) sh[0] = s;
    }
    __syncthreads();
    return sh[0];
}

__global__ void rownorm_split(const float* __restrict__ xq,
                              __nv_bfloat16* __restrict__ psis) {
    const int row = blockIdx.x;
    const float* p = xq + (size_t)row * DIM;
    const int t = threadIdx.x;
    float v0 = p[t], v1 = p[t+256], v2 = p[t+512], v3 = p[t+768];
    float ss = blockReduceSum256(v0*v0 + v1*v1 + v2*v2 + v3*v3);
    float sc = 1.f / fmaxf(sqrtf(ss), 1e-12f);
    __nv_bfloat16* out = psis + (size_t)row * K2;
    float vv[4] = {v0*sc, v1*sc, v2*sc, v3*sc};
    #pragma unroll
    for (int i = 0; i < 4; i++) {
        int k = t + i*256;
        __nv_bfloat16 h, l; split2(vv[i], h, l);
        out[k] = h; out[1024 + k] = h; out[2048 + k] = l;
    }
}

__global__ void layernorm(const float* __restrict__ in,
                          const float* __restrict__ w, const float* __restrict__ b,
                          float* __restrict__ out) {
    const int row = blockIdx.x;
    const float* p = in + (size_t)row * D_MODEL;
    const int t = threadIdx.x;
    float v0 = p[t], v1 = p[t+256];
    float mu = blockReduceSum256(v0 + v1) * (1.f / D_MODEL);
    float d0 = v0 - mu, d1 = v1 - mu;
    float var = blockReduceSum256(d0*d0 + d1*d1) * (1.f / D_MODEL);
    float inv = rsqrtf(var + 1e-5f);
    float* o = out + (size_t)row * D_MODEL;
    o[t]     = d0 * inv * w[t]     + b[t];
    o[t+256] = d1 * inv * w[t+256] + b[t+256];
}

// ---------------- launch ---------------------------------------------------------
extern "C" void kernel_launch(void* const* d_in, const int* in_sizes, int n_in,
                              void* d_out, int out_size) {
    const float* x     = (const float*)d_in[0];
    const float* W_in  = (const float*)d_in[1];
    const float* b_in  = (const float*)d_in[2];
    const float* W_out = (const float*)d_in[3];
    const float* b_out = (const float*)d_in[4];
    const float* rot   = (const float*)d_in[5];
    const float* ent   = (const float*)d_in[6];
    const float* ln_w  = (const float*)d_in[7];
    const float* ln_b  = (const float*)d_in[8];
    float* out = (float*)d_out;

    float *Ur, *Ui, *xq, *pre;
    __nv_bfloat16 *xs, *Wins, *psis, *U2, *P, *Wouts;
    cudaGetSymbolAddress((void**)&Ur,    g_Ur);
    cudaGetSymbolAddress((void**)&Ui,    g_Ui);
    cudaGetSymbolAddress((void**)&xq,    g_xq);
    cudaGetSymbolAddress((void**)&pre,   g_pre);
    cudaGetSymbolAddress((void**)&xs,    g_xs);
    cudaGetSymbolAddress((void**)&Wins,  g_Wins);
    cudaGetSymbolAddress((void**)&psis,  g_psis);
    cudaGetSymbolAddress((void**)&U2,    g_U2);
    cudaGetSymbolAddress((void**)&P,     g_P);
    cudaGetSymbolAddress((void**)&Wouts, g_Wouts);

    cudaFuncSetAttribute(gemm_mma<0>, cudaFuncAttributeMaxDynamicSharedMemorySize, SMEM_TOTAL);
    cudaFuncSetAttribute(gemm_mma<1>, cudaFuncAttributeMaxDynamicSharedMemorySize, SMEM_TOTAL);

    build_unitary<<<DIM, 256>>>(rot, ent, Ur, Ui);
    pack_U<<<(2048*DIM + 255)/256, 256>>>(Ur, Ui, U2);
    split_x<<<(N_TOKENS*D_MODEL + 255)/256, 256>>>(x, xs);
    split_Win<<<(DIM*D_MODEL + 255)/256, 256>>>(W_in, Wins);
    split_Wout<<<(D_MODEL*DIM + 255)/256, 256>>>(W_out, Wouts);

    // GEMM1: xq = x @ W_in^T + b_in  (K'=1536)
    gemm_mma<0><<<dim3(DIM/BN, N_TOKENS/BM), 256, SMEM_TOTAL>>>(
        xs, Wins, xq, nullptr, b_in, N_TOKENS, DIM, K1);

    // normalize + split -> psis (K'=3072)
    rownorm_split<<<N_TOKENS, 256>>>(xq, psis);

    // GEMM2: (re,im) interleaved vs U2 (N=2048); epilogue emits P = split probs
    gemm_mma<1><<<dim3(2048/BN, N_TOKENS/BM), 256, SMEM_TOTAL>>>(
        psis, U2, nullptr, P, nullptr, N_TOKENS, 2048, K2);

    // GEMM3: pre = probs @ W_out^T + b_out
    gemm_mma<0><<<dim3(D_MODEL/BN, N_TOKENS/BM), 256, SMEM_TOTAL>>>(
        P, Wouts, pre, nullptr, b_out, N_TOKENS, D_MODEL, K2);

    layernorm<<<N_TOKENS, 256>>>(pre, ln_w, ln_b, out);
}

// round 5
// speedup vs baseline: 2.9572x; 1.1424x over previous
#include <cuda_runtime.h>
#include <cuda_bf16.h>
#include <math.h>
#include <stdint.h>

#define N_TOKENS 16384
#define D_MODEL  512
#define NQ       10
#define NL       2
#define DIM      1024
#define K1       1536   // 3*512
#define K2       3072   // 3*1024

#define BM 128
#define BN 256
#define BKB 128                    // K bytes per stage (64 bf16)
#define NSTAGES 4
#define TILE_A (BM*BKB)            // 16 KB
#define TILE_Bb (BN*BKB)           // 32 KB
#define STAGE_B (TILE_A+TILE_Bb)   // 48 KB
#define SMEM_TOTAL (NSTAGES*STAGE_B)   // 192 KB

__device__ __align__(16) float          g_Ur[DIM*DIM];
__device__ __align__(16) float          g_Ui[DIM*DIM];
__device__ __align__(16) float          g_xq[N_TOKENS*DIM];
__device__ __align__(16) float          g_pre[N_TOKENS*D_MODEL];
__device__ __align__(16) __nv_bfloat16  g_xs[N_TOKENS*K1];
__device__ __align__(16) __nv_bfloat16  g_Wins[DIM*K1];
__device__ __align__(16) __nv_bfloat16  g_psis[N_TOKENS*K2];
__device__ __align__(16) __nv_bfloat16  g_U2[2048*K2];
__device__ __align__(16) __nv_bfloat16  g_P[N_TOKENS*K2];
__device__ __align__(16) __nv_bfloat16  g_Wouts[D_MODEL*K2];

// ---------------- PTX helpers (sm_80-era only; no 'a' features) --------------
__device__ __forceinline__ uint32_t smem_u32(const void* p) {
    return (uint32_t)__cvta_generic_to_shared(p);
}
#define CP16(saddr, gaddr) \
    asm volatile("cp.async.cg.shared.global [%0], [%1], 16;" \
                 :: "r"(saddr), "l"(gaddr) : "memory")
#define CP_COMMIT() asm volatile("cp.async.commit_group;" ::: "memory")
#define CP_WAIT2()  asm volatile("cp.async.wait_group 2;" ::: "memory")

#define LDSM4(r0,r1,r2,r3,addr) \
    asm volatile("ldmatrix.sync.aligned.m8n8.x4.shared.b16 {%0,%1,%2,%3}, [%4];" \
                 : "=r"(r0), "=r"(r1), "=r"(r2), "=r"(r3) : "r"(addr))

#define MMA16816(c, a0,a1,a2,a3, b0,b1) \
    asm volatile("mma.sync.aligned.m16n8k16.row.col.f32.bf16.bf16.f32 " \
                 "{%0,%1,%2,%3}, {%4,%5,%6,%7}, {%8,%9}, {%0,%1,%2,%3};" \
                 : "+f"((c)[0]), "+f"((c)[1]), "+f"((c)[2]), "+f"((c)[3]) \
                 : "r"(a0), "r"(a1), "r"(a2), "r"(a3), "r"(b0), "r"(b1))

#define SW128(off) ((off) ^ (((off) >> 3) & 0x70))

// ---------------- bf16 mma GEMM (128x256 tile, 64x64 warp tile) --------------
// C[M,N] = A[M,Kp] @ B[N,Kp]^T ; A,B bf16 K-major. EPI=0: C fp32 (+bias).
// EPI=1: output cols are (re,im) pairs -> prob = re^2+im^2, split to bf16
//        hi/lo and written to P[M,K2] segments [hi|hi|lo].
template<int EPI>
__global__ __launch_bounds__(256, 1)
void gemm_mma(const __nv_bfloat16* __restrict__ A,
              const __nv_bfloat16* __restrict__ B,
              float* __restrict__ C,
              __nv_bfloat16* __restrict__ P,
              const float* __restrict__ bias,
              int M, int N, int Kp)
{
    extern __shared__ char smem[];
    const uint32_t S0 = smem_u32(smem);
    const int tid  = threadIdx.x;
    const int wid  = tid >> 5;
    const int lane = tid & 31;
    const int warp_m = (wid & 1) * 64;   // 2 warps along M (64 rows each)
    const int warp_n = (wid >> 1) * 64;  // 4 warps along N (64 cols each)
    const int m0 = blockIdx.y * BM;
    const int n0 = blockIdx.x * BN;
    const int nks = Kp / 64;

    const size_t ldb = (size_t)Kp * 2;
    const size_t Ab = (size_t)__cvta_generic_to_global(A) + (size_t)m0 * ldb;
    const size_t Bb = (size_t)__cvta_generic_to_global(B) + (size_t)n0 * ldb;

    float c[4][8][4];
    #pragma unroll
    for (int mt = 0; mt < 4; mt++)
        #pragma unroll
        for (int nt = 0; nt < 8; nt++)
            #pragma unroll
            for (int j = 0; j < 4; j++) c[mt][nt][j] = 0.f;

    // per-stage load map: 3072 16B-chunks, 12 per thread
    // c < 1024 -> A (row c>>3), else B (row (c-1024)>>3)
    #pragma unroll
    for (int s = 0; s < NSTAGES - 1; s++) {
        const uint32_t saA = S0 + s * STAGE_B;
        const uint32_t saB = saA + TILE_A;
        const size_t ka = Ab + (size_t)s * BKB;
        const size_t kb = Bb + (size_t)s * BKB;
        #pragma unroll
        for (int i = 0; i < 12; i++) {
            int cc = tid + 256 * i;
            if (cc < 1024) {
                int r = cc >> 3, p = (cc & 7) * 16;
                CP16(saA + SW128(r*128 + p), ka + (size_t)r * ldb + p);
            } else {
                int c2 = cc - 1024;
                int r = c2 >> 3, p = (c2 & 7) * 16;
                CP16(saB + SW128(r*128 + p), kb + (size_t)r * ldb + p);
            }
        }
        CP_COMMIT();
    }

    for (int ks = 0; ks < nks; ks++) {
        CP_WAIT2();
        __syncthreads();

        int ld = ks + NSTAGES - 1;
        if (ld < nks) {
            int slot = ld % NSTAGES;
            const uint32_t saA = S0 + slot * STAGE_B;
            const uint32_t saB = saA + TILE_A;
            const size_t ka = Ab + (size_t)ld * BKB;
            const size_t kb = Bb + (size_t)ld * BKB;
            #pragma unroll
            for (int i = 0; i < 12; i++) {
                int cc = tid + 256 * i;
                if (cc < 1024) {
                    int r = cc >> 3, p = (cc & 7) * 16;
                    CP16(saA + SW128(r*128 + p), ka + (size_t)r * ldb + p);
                } else {
                    int c2 = cc - 1024;
                    int r = c2 >> 3, p = (c2 & 7) * 16;
                    CP16(saB + SW128(r*128 + p), kb + (size_t)r * ldb + p);
                }
            }
        }
        CP_COMMIT();

        const uint32_t saA = S0 + (ks % NSTAGES) * STAGE_B;
        const uint32_t saB = saA + TILE_A;
        #pragma unroll
        for (int kk = 0; kk < 4; kk++) {
            uint32_t a[4][4], b[4][4];
            #pragma unroll
            for (int mt2 = 0; mt2 < 2; mt2++) {
                int r = warp_m + mt2*32 + (lane & 31);
                // two 16-row ldsm.x4 per 32 rows: use m16 pairs
                uint32_t ad = saA + SW128(r*128 + kk*32);
                (void)ad;
            }
            // A fragments: 4 x (16 rows): rows warp_m + mt*16 + (lane&15)
            #pragma unroll
            for (int mt = 0; mt < 4; mt++) {
                int r = warp_m + mt*16 + (lane & 15);
                uint32_t ad = saA + SW128(r*128 + kk*32 + ((lane >> 4) << 4));
                LDSM4(a[mt][0], a[mt][1], a[mt][2], a[mt][3], ad);
            }
            // B fragments: 4 x (16 cols)
            #pragma unroll
            for (int nt2 = 0; nt2 < 4; nt2++) {
                int r = warp_n + nt2*16 + (lane & 7) + ((lane >> 4) << 3);
                uint32_t bd = saB + SW128(r*128 + kk*32 + (((lane >> 3) & 1) << 4));
                LDSM4(b[nt2][0], b[nt2][1], b[nt2][2], b[nt2][3], bd);
            }
            #pragma unroll
            for (int mt = 0; mt < 4; mt++)
                #pragma unroll
                for (int nt = 0; nt < 8; nt++)
                    MMA16816(c[mt][nt], a[mt][0], a[mt][1], a[mt][2], a[mt][3],
                             b[nt >> 1][(nt & 1) * 2], b[nt >> 1][(nt & 1) * 2 + 1]);
        }
    }

    // ---- epilogue ----
    #pragma unroll
    for (int mt = 0; mt < 4; mt++) {
        int r0 = m0 + warp_m + mt*16 + (lane >> 2);
        #pragma unroll
        for (int nt = 0; nt < 8; nt++) {
            if (EPI == 0) {
                int nn = n0 + warp_n + nt*8 + 2*(lane & 3);
                float b0 = bias ? bias[nn] : 0.f;
                float b1 = bias ? bias[nn+1] : 0.f;
                float2 v0 = make_float2(c[mt][nt][0] + b0, c[mt][nt][1] + b1);
                float2 v1 = make_float2(c[mt][nt][2] + b0, c[mt][nt][3] + b1);
                *(float2*)(C + (size_t)r0 * N + nn) = v0;
                *(float2*)(C + (size_t)(r0+8) * N + nn) = v1;
            } else {
                int pcol = ((n0 + warp_n + nt*8) >> 1) + (lane & 3);
                float p0 = c[mt][nt][0]*c[mt][nt][0] + c[mt][nt][1]*c[mt][nt][1];
                float p1 = c[mt][nt][2]*c[mt][nt][2] + c[mt][nt][3]*c[mt][nt][3];
                __nv_bfloat16 h0 = __float2bfloat16(p0);
                __nv_bfloat16 l0 = __float2bfloat16(p0 - __bfloat162float(h0));
                __nv_bfloat16 h1 = __float2bfloat16(p1);
                __nv_bfloat16 l1 = __float2bfloat16(p1 - __bfloat162float(h1));
                __nv_bfloat16* pr0 = P + (size_t)r0 * K2 + pcol;
                __nv_bfloat16* pr1 = P + (size_t)(r0+8) * K2 + pcol;
                pr0[0] = h0; pr0[1024] = h0; pr0[2048] = l0;
                pr1[0] = h1; pr1[1024] = h1; pr1[2048] = l1;
            }
        }
    }
}

// ---------------- circuit unitary ---------------------------------------------
__device__ __forceinline__ float2 cmul(float2 a, float2 b) {
    return make_float2(a.x*b.x - a.y*b.y, a.x*b.y + a.y*b.x);
}
__device__ __forceinline__ float2 cadd(float2 a, float2 b) {
    return make_float2(a.x + b.x, a.y + b.y);
}

__global__ void build_unitary(const float* __restrict__ rot,
                              const float* __restrict__ ent,
                              float* __restrict__ Ur, float* __restrict__ Ui) {
    __shared__ float2 st[DIM];
    const int j = blockIdx.x;
    const int t = threadIdx.x;
    for (int i = t; i < DIM; i += 256)
        st[i] = make_float2(i == j ? 1.f : 0.f, 0.f);
    __syncthreads();
    for (int l = 0; l < NL; l++) {
        for (int q = 0; q < NQ; q++) {
            const float t1 = rot[(l*NQ + q)*3 + 0];
            const float t2 = rot[(l*NQ + q)*3 + 1];
            const float t3 = rot[(l*NQ + q)*3 + 2];
            float c1, s1; sincosf(0.5f*t1, &s1, &c1);
            float2 rx00 = {c1,0.f}, rx01 = {0.f,-s1}, rx10 = {0.f,-s1}, rx11 = {c1,0.f};
            float c2, s2; sincosf(0.5f*t2, &s2, &c2);
            float2 ry00 = {c2,0.f}, ry01 = {-s2,0.f}, ry10 = {s2,0.f}, ry11 = {c2,0.f};
            float2 a00 = cadd(cmul(ry00,rx00), cmul(ry01,rx10));
            float2 a01 = cadd(cmul(ry00,rx01), cmul(ry01,rx11));
            float2 a10 = cadd(cmul(ry10,rx00), cmul(ry11,rx10));
            float2 a11 = cadd(cmul(ry10,rx01), cmul(ry11,rx11));
            float cz, sz; sincosf(0.5f*t3, &sz, &cz);
            float2 ez0 = {cz,-sz}, ez1 = {cz,sz};
            float2 m00 = cmul(ez0,a00), m01 = cmul(ez0,a01);
            float2 m10 = cmul(ez1,a10), m11 = cmul(ez1,a11);
            const int mask = 1 << (NQ - 1 - q);
            for (int p = t; p < DIM/2; p += 256) {
                int i0 = ((p & ~(mask-1)) << 1) | (p & (mask-1));
                int i1 = i0 | mask;
                float2 v0 = st[i0], v1 = st[i1];
                st[i0] = cadd(cmul(m00,v0), cmul(m01,v1));
                st[i1] = cadd(cmul(m10,v0), cmul(m11,v1));
            }
            __syncthreads();
        }
        for (int i = t; i < DIM; i += 256) {
            float ang = 0.f;
            #pragma unroll
            for (int g = 0; g < NQ-1; g++) {
                int b1 = (i >> (NQ-1-g)) & 1;
                int b2 = (i >> (NQ-2-g)) & 1;
                if (b1 & b2) ang += ent[l*(NQ-1) + g];
            }
            float sn, cs; sincosf(ang, &sn, &cs);
            st[i] = cmul(st[i], make_float2(cs, sn));
        }
        __syncthreads();
    }
    for (int i = t; i < DIM; i += 256) {
        Ur[i*DIM + j] = st[i].x;
        Ui[i*DIM + j] = st[i].y;
    }
}

// ---------------- split / pack ------------------------------------------------
__device__ __forceinline__ void split2(float v, __nv_bfloat16& h, __nv_bfloat16& l) {
    h = __float2bfloat16(v);
    l = __float2bfloat16(v - __bfloat162float(h));
}

__global__ void split_x(const float* __restrict__ x, __nv_bfloat16* __restrict__ xs) {
    int i = blockIdx.x * blockDim.x + threadIdx.x;
    if (i >= N_TOKENS * D_MODEL) return;
    int m = i / D_MODEL, k = i % D_MODEL;
    __nv_bfloat16 h, l; split2(x[i], h, l);
    __nv_bfloat16* row = xs + (size_t)m * K1;
    row[k] = h; row[512 + k] = h; row[1024 + k] = l;
}

__global__ void split_Win(const float* __restrict__ W, __nv_bfloat16* __restrict__ Ws) {
    int i = blockIdx.x * blockDim.x + threadIdx.x;
    if (i >= DIM * D_MODEL) return;
    int n = i / D_MODEL, k = i % D_MODEL;
    __nv_bfloat16 h, l; split2(W[i], h, l);
    __nv_bfloat16* row = Ws + (size_t)n * K1;
    row[k] = h; row[512 + k] = l; row[1024 + k] = h;
}

__global__ void split_Wout(const float* __restrict__ W, __nv_bfloat16* __restrict__ Ws) {
    int i = blockIdx.x * blockDim.x + threadIdx.x;
    if (i >= D_MODEL * DIM) return;
    int n = i / DIM, k = i % DIM;
    __nv_bfloat16 h, l; split2(W[i], h, l);
    __nv_bfloat16* row = Ws + (size_t)n * K2;
    row[k] = h; row[1024 + k] = l; row[2048 + k] = h;
}

// U2 rows: 2j = Ur[j,:], 2j+1 = Ui[j,:]; cols [hi|lo|hi]
__global__ void pack_U(const float* __restrict__ Ur, const float* __restrict__ Ui,
                       __nv_bfloat16* __restrict__ U2) {
    int i = blockIdx.x * blockDim.x + threadIdx.x;
    if (i >= 2048 * DIM) return;
    int n = i / DIM, k = i % DIM;
    int j = n >> 1;
    float v = (n & 1) ? Ui[(size_t)j*DIM + k] : Ur[(size_t)j*DIM + k];
    __nv_bfloat16 h, l; split2(v, h, l);
    __nv_bfloat16* row = U2 + (size_t)n * K2;
    row[k] = h; row[1024 + k] = l; row[2048 + k] = h;
}

// ---------------- reductions ----------------------------------------------------
__device__ float blockReduceSum256(float v) {
    __shared__ float sh[8];
    __syncthreads();
    int lane = threadIdx.x & 31, wid = threadIdx.x >> 5;
    #pragma unroll
    for (int o = 16; o > 0; o >>= 1) v += __shfl_down_sync(0xffffffffu, v, o);
    if (lane == 0) sh[wid] = v;
    __syncthreads();
    float s = 0.f;
    if (threadIdx.x < 8) s = sh[threadIdx.x];
    if (wid == 0) {
        #pragma unroll
        for (int o = 4; o > 0; o >>= 1) s += __shfl_down_sync(0xffu, s, o);
        if (lane == 0) sh[0] = s;
    }
    __syncthreads();
    return sh[0];
}

__global__ void rownorm_split(const float* __restrict__ xq,
                              __nv_bfloat16* __restrict__ psis) {
    const int row = blockIdx.x;
    const float* p = xq + (size_t)row * DIM;
    const int t = threadIdx.x;
    float v0 = p[t], v1 = p[t+256], v2 = p[t+512], v3 = p[t+768];
    float ss = blockReduceSum256(v0*v0 + v1*v1 + v2*v2 + v3*v3);
    float sc = 1.f / fmaxf(sqrtf(ss), 1e-12f);
    __nv_bfloat16* out = psis + (size_t)row * K2;
    float vv[4] = {v0*sc, v1*sc, v2*sc, v3*sc};
    #pragma unroll
    for (int i = 0; i < 4; i++) {
        int k = t + i*256;
        __nv_bfloat16 h, l; split2(vv[i], h, l);
        out[k] = h; out[1024 + k] = h; out[2048 + k] = l;
    }
}

__global__ void layernorm(const float* __restrict__ in,
                          const float* __restrict__ w, const float* __restrict__ b,
                          float* __restrict__ out) {
    const int row = blockIdx.x;
    const float* p = in + (size_t)row * D_MODEL;
    const int t = threadIdx.x;
    float v0 = p[t], v1 = p[t+256];
    float mu = blockReduceSum256(v0 + v1) * (1.f / D_MODEL);
    float d0 = v0 - mu, d1 = v1 - mu;
    float var = blockReduceSum256(d0*d0 + d1*d1) * (1.f / D_MODEL);
    float inv = rsqrtf(var + 1e-5f);
    float* o = out + (size_t)row * D_MODEL;
    o[t]     = d0 * inv * w[t]     + b[t];
    o[t+256] = d1 * inv * w[t+256] + b[t+256];
}

// ---------------- launch ---------------------------------------------------------
extern "C" void kernel_launch(void* const* d_in, const int* in_sizes, int n_in,
                              void* d_out, int out_size) {
    const float* x     = (const float*)d_in[0];
    const float* W_in  = (const float*)d_in[1];
    const float* b_in  = (const float*)d_in[2];
    const float* W_out = (const float*)d_in[3];
    const float* b_out = (const float*)d_in[4];
    const float* rot   = (const float*)d_in[5];
    const float* ent   = (const float*)d_in[6];
    const float* ln_w  = (const float*)d_in[7];
    const float* ln_b  = (const float*)d_in[8];
    float* out = (float*)d_out;

    float *Ur, *Ui, *xq, *pre;
    __nv_bfloat16 *xs, *Wins, *psis, *U2, *P, *Wouts;
    cudaGetSymbolAddress((void**)&Ur,    g_Ur);
    cudaGetSymbolAddress((void**)&Ui,    g_Ui);
    cudaGetSymbolAddress((void**)&xq,    g_xq);
    cudaGetSymbolAddress((void**)&pre,   g_pre);
    cudaGetSymbolAddress((void**)&xs,    g_xs);
    cudaGetSymbolAddress((void**)&Wins,  g_Wins);
    cudaGetSymbolAddress((void**)&psis,  g_psis);
    cudaGetSymbolAddress((void**)&U2,    g_U2);
    cudaGetSymbolAddress((void**)&P,     g_P);
    cudaGetSymbolAddress((void**)&Wouts, g_Wouts);

    cudaFuncSetAttribute(gemm_mma<0>, cudaFuncAttributeMaxDynamicSharedMemorySize, SMEM_TOTAL);
    cudaFuncSetAttribute(gemm_mma<1>, cudaFuncAttributeMaxDynamicSharedMemorySize, SMEM_TOTAL);

    build_unitary<<<DIM, 256>>>(rot, ent, Ur, Ui);
    pack_U<<<(2048*DIM + 255)/256, 256>>>(Ur, Ui, U2);
    split_x<<<(N_TOKENS*D_MODEL + 255)/256, 256>>>(x, xs);
    split_Win<<<(DIM*D_MODEL + 255)/256, 256>>>(W_in, Wins);
    split_Wout<<<(D_MODEL*DIM + 255)/256, 256>>>(W_out, Wouts);

    // GEMM1: xq = x @ W_in^T + b_in  (K'=1536)
    gemm_mma<0><<<dim3(DIM/BN, N_TOKENS/BM), 256, SMEM_TOTAL>>>(
        xs, Wins, xq, nullptr, b_in, N_TOKENS, DIM, K1);

    // normalize + split -> psis (K'=3072)
    rownorm_split<<<N_TOKENS, 256>>>(xq, psis);

    // GEMM2: (re,im) interleaved vs U2 (N=2048); epilogue emits P = split probs
    gemm_mma<1><<<dim3(2048/BN, N_TOKENS/BM), 256, SMEM_TOTAL>>>(
        psis, U2, nullptr, P, nullptr, N_TOKENS, 2048, K2);

    // GEMM3: pre = probs @ W_out^T + b_out
    gemm_mma<0><<<dim3(D_MODEL/BN, N_TOKENS/BM), 256, SMEM_TOTAL>>>(
        P, Wouts, pre, nullptr, b_out, N_TOKENS, D_MODEL, K2);

    layernorm<<<N_TOKENS, 256>>>(pre, ln_w, ln_b, out);
}